// round 1
// baseline (speedup 1.0000x reference)
#include <cuda_runtime.h>
#include <math.h>

#define NEG_INF (-1e10f)
#define BATCH 4
#define NN 1024
#define DD 32
#define WPR 32   // u32 words per bitset row

// ~512KB bitset scratch + 16KB group-max scratch (device globals: allowed)
__device__ unsigned g_bits[BATCH * NN * WPR];
__device__ float    g_gm[BATCH * 32 * DD];   // [b][group][d]

// ---------------------------------------------------------------------------
// Pack edges [B,N,N] int32 (0/1) -> bitset rows [B,N, 32 x u32]
// One warp per row; coalesced 128B loads; ballot per 32-column chunk.
// ---------------------------------------------------------------------------
__global__ void pack_kernel(const int* __restrict__ edges) {
    int warpId = (blockIdx.x * blockDim.x + threadIdx.x) >> 5;
    int lane   = threadIdx.x & 31;
    if (warpId >= BATCH * NN) return;
    const int* row = edges + (size_t)warpId * NN;
    unsigned myword = 0u;
    #pragma unroll
    for (int w = 0; w < 32; ++w) {
        unsigned word = __ballot_sync(0xFFFFFFFFu, row[w * 32 + lane] != 0);
        if (lane == w) myword = word;   // lane w keeps word w
    }
    g_bits[warpId * WPR + lane] = myword;   // coalesced 128B store
}

// ---------------------------------------------------------------------------
// Group maxes: gm[b][g][d] = max_{j in [g*32,(g+1)*32)} feat[b][j][d]
// ---------------------------------------------------------------------------
__global__ void gmax_kernel(const float* __restrict__ feat) {
    int b = blockIdx.x >> 5;
    int g = blockIdx.x & 31;
    int d = threadIdx.x;                  // 32 threads, d = lane
    const float* f = feat + ((size_t)b * NN + (size_t)g * 32) * DD + d;
    float m = f[0];
    #pragma unroll
    for (int j = 1; j < 32; ++j) m = fmaxf(m, f[j * DD]);
    g_gm[(b * 32 + g) * DD + d] = m;
}

// ---------------------------------------------------------------------------
// Fused E2-row construction (boolean square with saturation early-exit)
// + masked max-pool using group maxes.
// Grid: (32, BATCH), 256 threads. Block loads one batch's bitset into smem.
// ---------------------------------------------------------------------------
#define POOL_SMEM (NN * WPR * 4 + 32 * DD * 4)   // 131072 + 4096 = 135168 B

__global__ __launch_bounds__(256, 1)
void pool_kernel(const float* __restrict__ feat, float* __restrict__ out) {
    extern __shared__ unsigned smem[];
    unsigned* sbits = smem;                       // NN*WPR words
    float*    sgm   = (float*)(smem + NN * WPR);  // 32*DD floats

    const int b       = blockIdx.y;
    const int rowBase = blockIdx.x * 32;
    const int tid  = threadIdx.x;
    const int lane = tid & 31;
    const int warp = tid >> 5;

    // Stage batch bitset (128KB) + group maxes (4KB) into smem, vectorized.
    {
        const uint4* src = (const uint4*)(g_bits + (size_t)b * NN * WPR);
        uint4* dst = (uint4*)sbits;
        #pragma unroll 4
        for (int i = tid; i < NN * WPR / 4; i += 256) dst[i] = src[i];
        const float* gsrc = g_gm + b * 32 * DD;
        for (int i = tid; i < 32 * DD; i += 256) sgm[i] = gsrc[i];
    }
    __syncthreads();

    const float* fb = feat + (size_t)b * NN * DD;

    // Each warp handles 4 consecutive rows.
    for (int r = 0; r < 4; ++r) {
        const int i = rowBase + warp * 4 + r;

        // --- build E2 row i: acc (lane holds word `lane`) ---
        const unsigned rw = sbits[i * WPR + lane];   // row i of E
        unsigned acc = 0u;
        for (int w = 0; w < 32; ++w) {
            unsigned m = __shfl_sync(0xFFFFFFFFu, rw, w);  // warp-uniform
            while (m) {
                int k = (w << 5) + (__ffs(m) - 1);
                m &= m - 1;
                acc |= sbits[(k << 5) + lane];             // conflict-free LDS
            }
            // Saturation: once all 1024 bits set, more ORs are no-ops.
            if (__all_sync(0xFFFFFFFFu, acc == 0xFFFFFFFFu)) break;
        }

        // --- masked max-pool over j, lane = feature dim d ---
        float best = -INFINITY;
        #pragma unroll 4
        for (int g = 0; g < 32; ++g) {
            const unsigned mg = __shfl_sync(0xFFFFFFFFu, acc, g); // uniform
            const float gmv = sgm[(g << 5) + lane];
            float v;
            if (mg == 0xFFFFFFFFu) {
                v = gmv;                       // all visible
            } else if (mg == 0u) {
                v = gmv + NEG_INF;             // all masked (exact: monotone)
            } else {
                v = -INFINITY;                 // rare mixed group: per-bit
                for (int jj = 0; jj < 32; ++jj) {
                    float fv = fb[(size_t)((g << 5) + jj) * DD + lane];
                    v = fmaxf(v, fv + (((mg >> jj) & 1u) ? 0.0f : NEG_INF));
                }
            }
            best = fmaxf(best, v);
        }
        out[((size_t)b * NN + i) * DD + lane] = best;   // coalesced 128B
    }
}

// ---------------------------------------------------------------------------
extern "C" void kernel_launch(void* const* d_in, const int* in_sizes, int n_in,
                              void* d_out, int out_size) {
    // Identify inputs by size (features: B*N*D = 131072, edges: B*N*N = 4194304)
    const float* feat;
    const int*   edges;
    if (in_sizes[0] == BATCH * NN * DD) {
        feat  = (const float*)d_in[0];
        edges = (const int*)d_in[1];
    } else {
        feat  = (const float*)d_in[1];
        edges = (const int*)d_in[0];
    }

    // Idempotent, not a stream op — safe under graph capture.
    cudaFuncSetAttribute(pool_kernel,
                         cudaFuncAttributeMaxDynamicSharedMemorySize, POOL_SMEM);

    pack_kernel<<<(BATCH * NN) / 8, 256>>>(edges);          // 512 blocks, 8 warps
    gmax_kernel<<<BATCH * 32, 32>>>(feat);                  // tiny
    pool_kernel<<<dim3(32, BATCH), 256, POOL_SMEM>>>(feat, (float*)d_out);

    (void)n_in; (void)out_size;
}

// round 3
// speedup vs baseline: 1.1864x; 1.1864x over previous
#include <cuda_runtime.h>
#include <math.h>

#define NEG_INF (-1e10f)
#define BATCH 4
#define NN 1024
#define DD 32
#define WPR 32   // u32 words per bitset row

#define PACK_BLOCKS (BATCH * NN / 8)        // 512, warp per row
#define GMAX_BLOCKS (BATCH * 32 / 8)        // 16,  warp per (b,group)

// 512KB bitset scratch + 16KB group-max scratch (device globals: allowed)
__device__ unsigned g_bits[BATCH * NN * WPR];
__device__ float    g_gm[BATCH * 32 * DD];   // [b][group][d]

// ---------------------------------------------------------------------------
// Fused: pack edges -> bitset rows (blocks [0,512)) + group maxes (blocks
// [512,528)). Pack: one warp per row, uint4 loads (MLP=8), shfl-OR reduce.
// ---------------------------------------------------------------------------
__global__ __launch_bounds__(256)
void pack_gmax_kernel(const int* __restrict__ edges,
                      const float* __restrict__ feat) {
    const int lane = threadIdx.x & 31;
    const int warp = threadIdx.x >> 5;

    if (blockIdx.x < PACK_BLOCKS) {
        const int rowId = blockIdx.x * 8 + warp;            // 0..4095
        const uint4* row = (const uint4*)(edges + (size_t)rowId * NN);
        unsigned myword = 0u;
        #pragma unroll
        for (int i = 0; i < 8; ++i) {
            // lane covers columns i*128 + lane*4 .. +3
            uint4 v = row[i * 32 + lane];
            unsigned nib = (unsigned)(v.x != 0)
                         | ((unsigned)(v.y != 0) << 1)
                         | ((unsigned)(v.z != 0) << 2)
                         | ((unsigned)(v.w != 0) << 3);
            unsigned val = nib << ((lane & 7) * 4);
            // OR-butterfly within each 8-lane group -> word (i*4 + lane>>3)
            val |= __shfl_xor_sync(0xFFFFFFFFu, val, 1);
            val |= __shfl_xor_sync(0xFFFFFFFFu, val, 2);
            val |= __shfl_xor_sync(0xFFFFFFFFu, val, 4);
            // lane 4i+g grabs word g of this iteration (held by lane g*8)
            unsigned w = __shfl_sync(0xFFFFFFFFu, val, (lane & 3) << 3);
            if ((lane >> 2) == i) myword = w;
        }
        g_bits[rowId * WPR + lane] = myword;                // coalesced
    } else {
        // group maxes: warp per (b,group); idx = b*32+g in [0,128)
        const int idx = (blockIdx.x - PACK_BLOCKS) * 8 + warp;
        const float* f = feat + (size_t)idx * 32 * DD + lane; // NN*DD = 32*(32*DD)
        float m = f[0];
        #pragma unroll
        for (int j = 1; j < 32; ++j) m = fmaxf(m, f[j * DD]);
        g_gm[idx * DD + lane] = m;
    }
}

// ---------------------------------------------------------------------------
// E2-row construction (boolean square with saturation early-exit, reading the
// L2-resident bitset directly) + masked max-pool via group maxes.
// Grid: (NN/8, BATCH), 256 threads, one warp per output row.
// ---------------------------------------------------------------------------
__global__ __launch_bounds__(256)
void pool_kernel(const float* __restrict__ feat, float* __restrict__ out) {
    __shared__ float sgm[32 * DD];   // 4KB: this batch's group maxes

    const int b    = blockIdx.y;
    const int tid  = threadIdx.x;
    const int lane = tid & 31;
    const int warp = tid >> 5;
    const int i    = blockIdx.x * 8 + warp;        // output row

    {   // stage 4KB group maxes
        const float4* src = (const float4*)(g_gm + b * 32 * DD);
        float4* dst = (float4*)sgm;
        dst[tid] = src[tid];                       // 256 * 16B = 4KB
    }
    __syncthreads();

    const unsigned* __restrict__ bb = g_bits + (size_t)b * NN * WPR;
    const float* fb = feat + (size_t)b * NN * DD;

    // --- build E2 row i: acc (lane holds word `lane`) ---
    const unsigned rw = bb[i * WPR + lane];        // row i of E
    unsigned acc = 0u;
    for (int w = 0; w < 32; ++w) {
        unsigned m = __shfl_sync(0xFFFFFFFFu, rw, w);      // warp-uniform
        while (m) {
            int k = (w << 5) + (__ffs(m) - 1);
            m &= m - 1;
            acc |= bb[(k << 5) + lane];                    // L2 hit, MLP high
        }
        // Saturation: once all 1024 bits set, further ORs are no-ops.
        if (__all_sync(0xFFFFFFFFu, acc == 0xFFFFFFFFu)) break;
    }

    // --- masked max-pool over j; lane = feature dim d ---
    float best = -INFINITY;
    #pragma unroll
    for (int g = 0; g < 32; ++g) {
        const unsigned mg = __shfl_sync(0xFFFFFFFFu, acc, g);  // uniform
        const float gmv = sgm[(g << 5) + lane];
        float v;
        if (mg == 0xFFFFFFFFu) {
            v = gmv;                        // whole group visible
        } else if (mg == 0u) {
            v = gmv + NEG_INF;              // whole group masked (exact)
        } else {
            v = -INFINITY;                  // rare mixed group: per-element
            for (int jj = 0; jj < 32; ++jj) {
                float fv = fb[(size_t)((g << 5) + jj) * DD + lane];
                v = fmaxf(v, fv + (((mg >> jj) & 1u) ? 0.0f : NEG_INF));
            }
        }
        best = fmaxf(best, v);
    }
    out[((size_t)b * NN + i) * DD + lane] = best;   // coalesced 128B/warp
}

// ---------------------------------------------------------------------------
extern "C" void kernel_launch(void* const* d_in, const int* in_sizes, int n_in,
                              void* d_out, int out_size) {
    const float* feat;
    const int*   edges;
    if (in_sizes[0] == BATCH * NN * DD) {
        feat  = (const float*)d_in[0];
        edges = (const int*)d_in[1];
    } else {
        feat  = (const float*)d_in[1];
        edges = (const int*)d_in[0];
    }

    pack_gmax_kernel<<<PACK_BLOCKS + GMAX_BLOCKS, 256>>>(edges, feat);
    pool_kernel<<<dim3(NN / 8, BATCH), 256>>>(feat, (float*)d_out);

    (void)n_in; (void)out_size;
}

// round 6
// speedup vs baseline: 1.3000x; 1.0957x over previous
#include <cuda_runtime.h>
#include <math.h>

#define NEG_INF (-1e10f)
#define BATCH 4
#define NN 1024
#define DD 32
#define WPR 32   // u32 words per bitset row
#define FULL 0xFFFFFFFFu

#define PACK_BLOCKS (BATCH * NN / 8)        // 512, warp per row
#define GMAX_BLOCKS (BATCH * 32 / 8)        // 16,  warp per (b,group)

// 512KB bitset scratch + 16KB group-max scratch (device globals: allowed)
__device__ unsigned g_bits[BATCH * NN * WPR];
__device__ float    g_gm[BATCH * 32 * DD];   // [b][group][d]

// ---------------------------------------------------------------------------
// Fused: pack edges -> bitset rows (blocks [0,512)) + group maxes (blocks
// [512,528)). Pack: one warp per row, uint4 loads (MLP=8), shfl-OR reduce.
// ---------------------------------------------------------------------------
__global__ __launch_bounds__(256)
void pack_gmax_kernel(const int* __restrict__ edges,
                      const float* __restrict__ feat) {
    const int lane = threadIdx.x & 31;
    const int warp = threadIdx.x >> 5;

    if (blockIdx.x < PACK_BLOCKS) {
        const int rowId = blockIdx.x * 8 + warp;            // 0..4095
        const uint4* row = (const uint4*)(edges + (size_t)rowId * NN);
        unsigned myword = 0u;
        #pragma unroll
        for (int i = 0; i < 8; ++i) {
            // lane covers columns i*128 + lane*4 .. +3
            uint4 v = row[i * 32 + lane];
            unsigned nib = (unsigned)(v.x != 0)
                         | ((unsigned)(v.y != 0) << 1)
                         | ((unsigned)(v.z != 0) << 2)
                         | ((unsigned)(v.w != 0) << 3);
            unsigned val = nib << ((lane & 7) * 4);
            // OR-butterfly within each 8-lane group -> word (i*4 + lane>>3)
            val |= __shfl_xor_sync(FULL, val, 1);
            val |= __shfl_xor_sync(FULL, val, 2);
            val |= __shfl_xor_sync(FULL, val, 4);
            // lane 4i+g grabs word g of this iteration (held by lane g*8)
            unsigned w = __shfl_sync(FULL, val, (lane & 3) << 3);
            if ((lane >> 2) == i) myword = w;
        }
        g_bits[rowId * WPR + lane] = myword;                // coalesced
    } else {
        // group maxes: warp per (b,group); idx = b*32+g in [0,128)
        const int idx = (blockIdx.x - PACK_BLOCKS) * 8 + warp;
        const float* f = feat + (size_t)idx * 32 * DD + lane;
        float m = f[0];
        #pragma unroll
        for (int j = 1; j < 32; ++j) m = fmaxf(m, f[j * DD]);
        g_gm[idx * DD + lane] = m;
    }
}

// ---------------------------------------------------------------------------
// E2-row construction: boolean square with 16-wide batched OR loads (MLP=16)
// and exact saturation early-exit, then masked max-pool.
// Saturated rows (the overwhelmingly common case here) take a shfl-free
// fast path: plain max over the 32 group-maxes.
// Grid: (NN/8, BATCH), 256 threads, one warp per output row.
// ---------------------------------------------------------------------------
__global__ __launch_bounds__(256)
void pool_kernel(const float* __restrict__ feat, float* __restrict__ out) {
    __shared__ float sgm[32 * DD];   // 4KB: this batch's group maxes

    const int b    = blockIdx.y;
    const int tid  = threadIdx.x;
    const int lane = tid & 31;
    const int warp = tid >> 5;
    const int i    = blockIdx.x * 8 + warp;        // output row

    const unsigned* __restrict__ bb = g_bits + (size_t)b * NN * WPR;
    const float* fb = feat + (size_t)b * NN * DD;

    // Issue the row-of-E load before the smem stage so it overlaps.
    const unsigned rw = bb[i * WPR + lane];        // row i of E

    ((float4*)sgm)[tid] = ((const float4*)(g_gm + b * 32 * DD))[tid];
    __syncthreads();

    // --- build E2 row i: acc (lane holds word `lane`) ---
    unsigned acc = 0u;
    bool sat = false;                              // warp-uniform
    for (int w = 0; w < 32 && !sat; ++w) {
        unsigned m = __shfl_sync(FULL, rw, w);     // warp-uniform word
        while (m && !sat) {
            // Pop up to 16 neighbors; addresses are ALU-only so all 16 LDGs
            // issue back-to-back (MLP=16) before the OR chain waits.
            unsigned v = 0u;
            #pragma unroll
            for (int t = 0; t < 16; ++t) {
                if (m) {
                    int k = (w << 5) + __ffs(m) - 1;
                    m &= m - 1u;
                    v |= bb[(k << 5) + lane];      // L2-hit, conflict-free
                }
            }
            acc |= v;
            // Exact: once all 1024 bits set, further ORs are no-ops.
            sat = __all_sync(FULL, acc == FULL);
        }
    }

    float best;
    if (sat) {
        // Everything visible: max over all group maxes (batch max).
        best = sgm[lane];
        #pragma unroll
        for (int g = 1; g < 32; ++g) best = fmaxf(best, sgm[(g << 5) + lane]);
    } else {
        best = -INFINITY;
        for (int g = 0; g < 32; ++g) {
            const unsigned mg = __shfl_sync(FULL, acc, g);   // uniform
            const float gmv = sgm[(g << 5) + lane];
            float v;
            if (mg == FULL) {
                v = gmv;                        // whole group visible
            } else if (mg == 0u) {
                v = gmv + NEG_INF;              // whole group masked (exact)
            } else {
                v = -INFINITY;                  // mixed group: per-element
                for (int jj = 0; jj < 32; ++jj) {
                    float fv = fb[(size_t)((g << 5) + jj) * DD + lane];
                    v = fmaxf(v, fv + (((mg >> jj) & 1u) ? 0.0f : NEG_INF));
                }
            }
            best = fmaxf(best, v);
        }
    }
    out[((size_t)b * NN + i) * DD + lane] = best;   // coalesced 128B/warp
}

// ---------------------------------------------------------------------------
extern "C" void kernel_launch(void* const* d_in, const int* in_sizes, int n_in,
                              void* d_out, int out_size) {
    const float* feat;
    const int*   edges;
    if (in_sizes[0] == BATCH * NN * DD) {
        feat  = (const float*)d_in[0];
        edges = (const int*)d_in[1];
    } else {
        feat  = (const float*)d_in[1];
        edges = (const int*)d_in[0];
    }

    pack_gmax_kernel<<<PACK_BLOCKS + GMAX_BLOCKS, 256>>>(edges, feat);
    pool_kernel<<<dim3(NN / 8, BATCH), 256>>>(feat, (float*)d_out);

    (void)n_in; (void)out_size;
}

// round 8
// speedup vs baseline: 1.5352x; 1.1809x over previous
#include <cuda_runtime.h>
#include <math.h>

#define NEG_INF (-1e10f)
#define BATCH 4
#define NN 1024
#define DD 32
#define WPR 32   // u32 words per bitset row
#define FULL 0xFFFFFFFFu

#define PACK_BLOCKS (BATCH * NN / 8)        // 512, warp per row
#define GMAX_BLOCKS (BATCH * 32 / 8)        // 16,  warp per (b,group)

// 512KB bitset scratch + 16KB group-max scratch (device globals: allowed)
__device__ unsigned g_bits[BATCH * NN * WPR];
__device__ float    g_gm[BATCH * 32 * DD];   // [b][group][d]

// ---------------------------------------------------------------------------
// Fused: pack edges -> bitset rows (blocks [0,512)) + group maxes (blocks
// [512,528)). Pack: one warp per row, uint4 loads (MLP=8), shfl-OR reduce.
// ---------------------------------------------------------------------------
__global__ __launch_bounds__(256)
void pack_gmax_kernel(const int* __restrict__ edges,
                      const float* __restrict__ feat) {
    const int lane = threadIdx.x & 31;
    const int warp = threadIdx.x >> 5;

    if (blockIdx.x < PACK_BLOCKS) {
        const int rowId = blockIdx.x * 8 + warp;            // 0..4095
        const uint4* row = (const uint4*)(edges + (size_t)rowId * NN);
        unsigned myword = 0u;
        #pragma unroll
        for (int i = 0; i < 8; ++i) {
            // lane covers columns i*128 + lane*4 .. +3
            uint4 v = row[i * 32 + lane];
            unsigned nib = (unsigned)(v.x != 0)
                         | ((unsigned)(v.y != 0) << 1)
                         | ((unsigned)(v.z != 0) << 2)
                         | ((unsigned)(v.w != 0) << 3);
            unsigned val = nib << ((lane & 7) * 4);
            // OR-butterfly within each 8-lane group -> word (i*4 + lane>>3)
            val |= __shfl_xor_sync(FULL, val, 1);
            val |= __shfl_xor_sync(FULL, val, 2);
            val |= __shfl_xor_sync(FULL, val, 4);
            // lane 4i+g grabs word g of this iteration (held by lane g*8)
            unsigned w = __shfl_sync(FULL, val, (lane & 3) << 3);
            if ((lane >> 2) == i) myword = w;
        }
        g_bits[rowId * WPR + lane] = myword;                // coalesced
    } else {
        // group maxes: warp per (b,group); idx = b*32+g in [0,128)
        const int idx = (blockIdx.x - PACK_BLOCKS) * 8 + warp;
        const float* f = feat + (size_t)idx * 32 * DD + lane;
        float m = f[0];
        #pragma unroll
        for (int j = 1; j < 32; ++j) m = fmaxf(m, f[j * DD]);
        g_gm[idx * DD + lane] = m;
    }
}

// ---------------------------------------------------------------------------
// E2-row construction: one full word of neighbors per round. Indices are
// precomputed into unrolled register arrays with an idempotent-duplicate
// fallback (re-ORing a neighbor row is a no-op), so all 32 LDGs per round
// are UNCONDITIONAL with ALU-only addresses -> ptxas front-batches them
// (true MLP~32). Exact saturation early-exit; exact general fallback.
// Grid: (NN/8, BATCH), 256 threads, one warp per output row.
// ---------------------------------------------------------------------------
__global__ __launch_bounds__(256)
void pool_kernel(const float* __restrict__ feat, float* __restrict__ out) {
    __shared__ float sgm[32 * DD];   // 4KB: this batch's group maxes

    const int b    = blockIdx.y;
    const int tid  = threadIdx.x;
    const int lane = tid & 31;
    const int warp = tid >> 5;
    const int i    = blockIdx.x * 8 + warp;        // output row

    const unsigned* __restrict__ bb = g_bits + (size_t)b * NN * WPR;
    const float* fb = feat + (size_t)b * NN * DD;

    // Issue the row-of-E load before the smem stage so it overlaps.
    const unsigned rw = bb[i * WPR + lane];        // row i of E

    ((float4*)sgm)[tid] = ((const float4*)(g_gm + b * 32 * DD))[tid];
    __syncthreads();

    // --- build E2 row i: acc (lane holds word `lane`) ---
    unsigned acc = 0u;
    bool sat = false;                              // warp-uniform
    for (int w = 0; w < 32 && !sat; ++w) {
        const unsigned m = __shfl_sync(FULL, rw, w);   // warp-uniform word
        if (!m) continue;
        const int base = w << 5;
        const int fallback = base + __ffs(m) - 1;      // a real neighbor

        // Two independent pop chains (halves) -> serial ffs depth 16 each.
        unsigned lo = m & 0xFFFFu;
        unsigned hi = m >> 16;
        int idxL[16], idxH[16];
        #pragma unroll
        for (int t = 0; t < 16; ++t) {
            idxL[t] = lo ? (base + __ffs(lo) - 1) : fallback;
            lo &= lo - 1u;
            idxH[t] = hi ? (base + 16 + __ffs(hi) - 1) : fallback;
            hi &= hi - 1u;
        }

        // 32 unconditional, independent LDGs; 4 accumulators keep the
        // consume chains shallow.
        unsigned v0 = 0u, v1 = 0u, v2 = 0u, v3 = 0u;
        #pragma unroll
        for (int t = 0; t < 16; t += 2) {
            v0 |= bb[(idxL[t]     << 5) + lane];
            v1 |= bb[(idxH[t]     << 5) + lane];
            v2 |= bb[(idxL[t + 1] << 5) + lane];
            v3 |= bb[(idxH[t + 1] << 5) + lane];
        }
        acc |= (v0 | v1) | (v2 | v3);
        // Exact: once all 1024 bits set, further ORs are no-ops.
        sat = __all_sync(FULL, acc == FULL);
    }

    float best;
    if (sat) {
        // Everything visible: max over all group maxes (batch max).
        best = sgm[lane];
        #pragma unroll
        for (int g = 1; g < 32; ++g) best = fmaxf(best, sgm[(g << 5) + lane]);
    } else {
        best = -INFINITY;
        for (int g = 0; g < 32; ++g) {
            const unsigned mg = __shfl_sync(FULL, acc, g);   // uniform
            const float gmv = sgm[(g << 5) + lane];
            float v;
            if (mg == FULL) {
                v = gmv;                        // whole group visible
            } else if (mg == 0u) {
                v = gmv + NEG_INF;              // whole group masked (exact)
            } else {
                v = -INFINITY;                  // mixed group: per-element
                for (int jj = 0; jj < 32; ++jj) {
                    float fv = fb[(size_t)((g << 5) + jj) * DD + lane];
                    v = fmaxf(v, fv + (((mg >> jj) & 1u) ? 0.0f : NEG_INF));
                }
            }
            best = fmaxf(best, v);
        }
    }
    out[((size_t)b * NN + i) * DD + lane] = best;   // coalesced 128B/warp
}

// ---------------------------------------------------------------------------
extern "C" void kernel_launch(void* const* d_in, const int* in_sizes, int n_in,
                              void* d_out, int out_size) {
    const float* feat;
    const int*   edges;
    if (in_sizes[0] == BATCH * NN * DD) {
        feat  = (const float*)d_in[0];
        edges = (const int*)d_in[1];
    } else {
        feat  = (const float*)d_in[1];
        edges = (const int*)d_in[0];
    }

    pack_gmax_kernel<<<PACK_BLOCKS + GMAX_BLOCKS, 256>>>(edges, feat);
    pool_kernel<<<dim3(NN / 8, BATCH), 256>>>(feat, (float*)d_out);

    (void)n_in; (void)out_size;
}

// round 10
// speedup vs baseline: 1.8185x; 1.1845x over previous
#include <cuda_runtime.h>
#include <math.h>

#define NEG_INF (-1e10f)
#define BATCH 4
#define NN 1024
#define DD 32
#define WPR 32   // u32 words per bitset row
#define FULL 0xFFFFFFFFu

#define PACK_BLOCKS (BATCH * NN / 8)        // 512, warp per row
#define GMAX_BLOCKS (BATCH * 32 / 8)        // 16,  warp per (b,group)

// 512KB bitset scratch + 16KB group-max scratch (device globals: allowed)
__device__ unsigned g_bits[BATCH * NN * WPR];
__device__ float    g_gm[BATCH * 32 * DD];   // [b][group][d]

// ---------------------------------------------------------------------------
// Fused: pack edges -> bitset rows (blocks [0,512)) + group maxes (blocks
// [512,528)). Pack: one warp per row, uint4 loads (MLP=8), shfl-OR reduce.
// ---------------------------------------------------------------------------
__global__ __launch_bounds__(256)
void pack_gmax_kernel(const int* __restrict__ edges,
                      const float* __restrict__ feat) {
    const int lane = threadIdx.x & 31;
    const int warp = threadIdx.x >> 5;

    if (blockIdx.x < PACK_BLOCKS) {
        const int rowId = blockIdx.x * 8 + warp;            // 0..4095
        const uint4* row = (const uint4*)(edges + (size_t)rowId * NN);
        unsigned myword = 0u;
        #pragma unroll
        for (int i = 0; i < 8; ++i) {
            // lane covers columns i*128 + lane*4 .. +3
            uint4 v = row[i * 32 + lane];
            unsigned nib = (unsigned)(v.x != 0)
                         | ((unsigned)(v.y != 0) << 1)
                         | ((unsigned)(v.z != 0) << 2)
                         | ((unsigned)(v.w != 0) << 3);
            unsigned val = nib << ((lane & 7) * 4);
            // OR-butterfly within each 8-lane group -> word (i*4 + lane>>3)
            val |= __shfl_xor_sync(FULL, val, 1);
            val |= __shfl_xor_sync(FULL, val, 2);
            val |= __shfl_xor_sync(FULL, val, 4);
            // lane 4i+g grabs word g of this iteration (held by lane g*8)
            unsigned w = __shfl_sync(FULL, val, (lane & 3) << 3);
            if ((lane >> 2) == i) myword = w;
        }
        g_bits[rowId * WPR + lane] = myword;                // coalesced
    } else {
        // group maxes: warp per (b,group); idx = b*32+g in [0,128)
        const int idx = (blockIdx.x - PACK_BLOCKS) * 8 + warp;
        const float* f = feat + (size_t)idx * 32 * DD + lane;
        float m = f[0];
        #pragma unroll
        for (int j = 1; j < 32; ++j) m = fmaxf(m, f[j * DD]);
        g_gm[idx * DD + lane] = m;
    }
}

// ---------------------------------------------------------------------------
// E2-row construction: one full word of neighbors per round. Lane t computes
// the (t+1)-th set bit of the word with HW __fns (one instruction, no arrays,
// no serial pop chain); lanes past popcount use an idempotent duplicate
// (re-ORing a row is a no-op -> exact). The load loop shfl-broadcasts each
// index and issues 32 mutually independent LDGs (true MLP, ~10 live regs).
// Exact saturation early-exit; exact general pooling fallback.
// Grid: (NN/8, BATCH), 256 threads, one warp per output row.
// ---------------------------------------------------------------------------
__global__ __launch_bounds__(256)
void pool_kernel(const float* __restrict__ feat, float* __restrict__ out) {
    __shared__ float sgm[32 * DD];   // 4KB: this batch's group maxes

    const int b    = blockIdx.y;
    const int tid  = threadIdx.x;
    const int lane = tid & 31;
    const int warp = tid >> 5;
    const int i    = blockIdx.x * 8 + warp;        // output row

    const unsigned* __restrict__ bb = g_bits + (size_t)b * NN * WPR;
    const float* fb = feat + (size_t)b * NN * DD;

    // Issue the row-of-E load before the smem stage so it overlaps.
    const unsigned rw = bb[i * WPR + lane];        // row i of E

    ((float4*)sgm)[tid] = ((const float4*)(g_gm + b * 32 * DD))[tid];
    __syncthreads();

    // --- build E2 row i: acc (lane holds word `lane`) ---
    unsigned acc = 0u;
    bool sat = false;                              // warp-uniform
    for (int w = 0; w < 32 && !sat; ++w) {
        const unsigned m = __shfl_sync(FULL, rw, w);   // warp-uniform word
        if (!m) continue;
        const int base = w << 5;
        const int fallback = base + __ffs(m) - 1;      // a real neighbor

        // Lane t: index of (t+1)-th set bit, else idempotent duplicate.
        const unsigned pos = __fns(m, 0, lane + 1);    // 0xFFFFFFFF if none
        const int myidx = (pos < 32u) ? (base + (int)pos) : fallback;

        // 32 independent (shfl -> LDG) chains; 4 accumulators keep the
        // consume chains shallow. Addresses are ALU/shfl-only.
        unsigned v0 = 0u, v1 = 0u, v2 = 0u, v3 = 0u;
        #pragma unroll
        for (int t = 0; t < 32; t += 4) {
            const int k0 = __shfl_sync(FULL, myidx, t);
            const int k1 = __shfl_sync(FULL, myidx, t + 1);
            const int k2 = __shfl_sync(FULL, myidx, t + 2);
            const int k3 = __shfl_sync(FULL, myidx, t + 3);
            v0 |= bb[(k0 << 5) + lane];
            v1 |= bb[(k1 << 5) + lane];
            v2 |= bb[(k2 << 5) + lane];
            v3 |= bb[(k3 << 5) + lane];
        }
        acc |= (v0 | v1) | (v2 | v3);
        // Exact: once all 1024 bits set, further ORs are no-ops.
        sat = __all_sync(FULL, acc == FULL);
    }

    float best;
    if (sat) {
        // Everything visible: max over all group maxes (batch max).
        best = sgm[lane];
        #pragma unroll
        for (int g = 1; g < 32; ++g) best = fmaxf(best, sgm[(g << 5) + lane]);
    } else {
        best = -INFINITY;
        for (int g = 0; g < 32; ++g) {
            const unsigned mg = __shfl_sync(FULL, acc, g);   // uniform
            const float gmv = sgm[(g << 5) + lane];
            float v;
            if (mg == FULL) {
                v = gmv;                        // whole group visible
            } else if (mg == 0u) {
                v = gmv + NEG_INF;              // whole group masked (exact)
            } else {
                v = -INFINITY;                  // mixed group: per-element
                for (int jj = 0; jj < 32; ++jj) {
                    float fv = fb[(size_t)((g << 5) + jj) * DD + lane];
                    v = fmaxf(v, fv + (((mg >> jj) & 1u) ? 0.0f : NEG_INF));
                }
            }
            best = fmaxf(best, v);
        }
    }
    out[((size_t)b * NN + i) * DD + lane] = best;   // coalesced 128B/warp
}

// ---------------------------------------------------------------------------
extern "C" void kernel_launch(void* const* d_in, const int* in_sizes, int n_in,
                              void* d_out, int out_size) {
    const float* feat;
    const int*   edges;
    if (in_sizes[0] == BATCH * NN * DD) {
        feat  = (const float*)d_in[0];
        edges = (const int*)d_in[1];
    } else {
        feat  = (const float*)d_in[1];
        edges = (const int*)d_in[0];
    }

    pack_gmax_kernel<<<PACK_BLOCKS + GMAX_BLOCKS, 256>>>(edges, feat);
    pool_kernel<<<dim3(NN / 8, BATCH), 256>>>(feat, (float*)d_out);

    (void)n_in; (void)out_size;
}